// round 16
// baseline (speedup 1.0000x reference)
#include <cuda_runtime.h>
#include <math.h>
#include <stdint.h>

#define MTOK 16384
#define DDIM 1024
#define CCLS 1000
#define LNUM 6
#define NBR  3
#define SDIM 64
#define KTOP 204
#define THRC 0.85f
#define SBK 32

__device__ float g_x[MTOK * DDIM];             // 64 MB
__device__ float g_h[MTOK * DDIM];             // 64 MB
__device__ float g_sims[NBR * MTOK * DDIM];    // 192 MB (R1/R15-proven guard-safe)
__device__ unsigned char g_active[MTOK];
__device__ int g_depth[MTOK];
__device__ float g_scores[NBR];
__device__ int g_best;
__device__ double g_vloss;

__device__ __forceinline__ float gelu_exact(float v) {
    return 0.5f * v * (1.0f + erff(v * 0.70710678118654752440f));
}

__global__ void init_kernel(const float* __restrict__ x) {
    int tid = blockIdx.x * blockDim.x + threadIdx.x, st = gridDim.x * blockDim.x;
    const float4* x4 = (const float4*)x;
    float4* g4 = (float4*)g_x;
    for (int i = tid; i < MTOK * DDIM / 4; i += st) g4[i] = x4[i];
    for (int i = tid; i < MTOK; i += st) { g_active[i] = 1; g_depth[i] = 0; }
    if (tid == 0) { g_vloss = 0.0; g_best = 0; g_scores[0] = g_scores[1] = g_scores[2] = 0.f; }
}

// ---------------- scalar fp32 SGEMM, BK=32, bitwise-R1 accumulation order ----------------
// Per output: single accumulator, pure ascending-k fmaf chain (k0 asc, kk asc) ->
// bit-identical to the R1 BK=16 kernel.
// ACT 1: C = gelu(v + bias), all rows (DCA h, CEN sims)
// ACT 2: C = v + bias, rows with actmask!=0 only (exit head -> d_out)
template <int ACT>
__global__ __launch_bounds__(256) void sgemm_kernel(
    const float* __restrict__ A, const float* __restrict__ B,
    const float* __restrict__ bias, float* __restrict__ C,
    int M, int N, int K, const unsigned char* __restrict__ actmask)
{
    __shared__ float As[SBK][132];   // [k][m] transposed
    __shared__ float Bs[SBK][128];   // [k][n]

    const int tid = threadIdx.x;
    const int bx = blockIdx.x, by = blockIdx.y;
    const float* Ab = A + (size_t)by * 128 * K;
    const int trow = tid >> 4, tcol = tid & 15;

    // load mapping: 4 float4 per thread for each of A and B
    const int arow[4] = {(tid + 0) >> 3, (tid + 256) >> 3, (tid + 512) >> 3, (tid + 768) >> 3};
    const int akq = tid & 7;                       // same for all i since stride 256 = 32*8
    const int bkr[4] = {(tid + 0) >> 5, (tid + 256) >> 5, (tid + 512) >> 5, (tid + 768) >> 5};
    const int bc4 = tid & 31;
    const int gcol = bx * 128 + bc4 * 4;
    const bool bok = (gcol + 3 < N);
    const float4 z4 = make_float4(0.f, 0.f, 0.f, 0.f);

    float acc[8][8];
#pragma unroll
    for (int i = 0; i < 8; i++)
#pragma unroll
        for (int j = 0; j < 8; j++) acc[i][j] = 0.f;

    float4 a[4], b[4];
#pragma unroll
    for (int i = 0; i < 4; i++) {
        a[i] = *(const float4*)(Ab + (size_t)arow[i] * K + akq * 4);
        b[i] = bok ? *(const float4*)(B + (size_t)bkr[i] * N + gcol) : z4;
    }

    for (int k0 = 0; k0 < K; k0 += SBK) {
#pragma unroll
        for (int i = 0; i < 4; i++) {
            As[akq * 4 + 0][arow[i]] = a[i].x;
            As[akq * 4 + 1][arow[i]] = a[i].y;
            As[akq * 4 + 2][arow[i]] = a[i].z;
            As[akq * 4 + 3][arow[i]] = a[i].w;
            *(float4*)&Bs[bkr[i]][bc4 * 4] = b[i];
        }
        __syncthreads();

        if (k0 + SBK < K) {
#pragma unroll
            for (int i = 0; i < 4; i++) {
                a[i] = *(const float4*)(Ab + (size_t)arow[i] * K + (k0 + SBK) + akq * 4);
                b[i] = bok ? *(const float4*)(B + (size_t)(k0 + SBK + bkr[i]) * N + gcol) : z4;
            }
        }

#pragma unroll
        for (int kk = 0; kk < SBK; kk++) {
            float4 ra0 = *(const float4*)&As[kk][trow * 4];
            float4 ra1 = *(const float4*)&As[kk][64 + trow * 4];
            float4 rb0 = *(const float4*)&Bs[kk][tcol * 4];
            float4 rb1 = *(const float4*)&Bs[kk][64 + tcol * 4];
            float ra[8] = {ra0.x, ra0.y, ra0.z, ra0.w, ra1.x, ra1.y, ra1.z, ra1.w};
            float rb[8] = {rb0.x, rb0.y, rb0.z, rb0.w, rb1.x, rb1.y, rb1.z, rb1.w};
#pragma unroll
            for (int i = 0; i < 8; i++)
#pragma unroll
                for (int j = 0; j < 8; j++) acc[i][j] = fmaf(ra[i], rb[j], acc[i][j]);
        }
        __syncthreads();
    }

#pragma unroll
    for (int i = 0; i < 8; i++) {
        int row = by * 128 + ((i < 4) ? (trow * 4 + i) : (64 + trow * 4 + (i - 4)));
        bool wr = (ACT == 1) || (actmask[row] != 0);
        if (!wr) continue;
#pragma unroll
        for (int jq = 0; jq < 2; jq++) {
            int col = bx * 128 + (jq ? (64 + tcol * 4) : (tcol * 4));
            if (col + 3 < N) {
                float v0 = acc[i][jq * 4 + 0] + bias[col + 0];
                float v1 = acc[i][jq * 4 + 1] + bias[col + 1];
                float v2 = acc[i][jq * 4 + 2] + bias[col + 2];
                float v3 = acc[i][jq * 4 + 3] + bias[col + 3];
                if (ACT == 1) {
                    v0 = gelu_exact(v0); v1 = gelu_exact(v1);
                    v2 = gelu_exact(v2); v3 = gelu_exact(v3);
                }
                *(float4*)(C + (size_t)row * N + col) = make_float4(v0, v1, v2, v3);
            } else {
#pragma unroll
                for (int e = 0; e < 4; e++) {
                    int cc = col + e;
                    if (cc < N) {
                        float v = acc[i][jq * 4 + e] + bias[cc];
                        if (ACT == 1) v = gelu_exact(v);
                        C[(size_t)row * N + cc] = v;
                    }
                }
            }
        }
    }
}

// ---------------- per-token exact top-K + masked residual add ----------------
__global__ void topk_kernel() {
    int row = blockIdx.x, tid = threadIdx.x;
    __shared__ float sh[DDIM];
    __shared__ int hist[256];
    __shared__ int s_k;
    __shared__ unsigned s_pref;
    const float* hr = g_h + (size_t)row * DDIM;
    for (int j = tid; j < DDIM; j += 256) sh[j] = hr[j];
    if (tid == 0) { s_k = KTOP; s_pref = 0u; }
    __syncthreads();
    for (int shift = 24; shift >= 0; shift -= 8) {
        hist[tid] = 0;
        __syncthreads();
        unsigned pref = s_pref;
        for (int j = tid; j < DDIM; j += 256) {
            unsigned b = __float_as_uint(fabsf(sh[j]));
            bool cand = (shift == 24) || ((b >> (shift + 8)) == pref);
            if (cand) atomicAdd(&hist[(b >> shift) & 255], 1);
        }
        __syncthreads();
        if (tid == 0) {
            int k = s_k, cum = 0, d = 255;
            for (; d >= 0; --d) { cum += hist[d]; if (cum >= k) break; }
            s_k = k - (cum - hist[d]);
            s_pref = (pref << 8) | (unsigned)d;
        }
        __syncthreads();
    }
    unsigned kb = s_pref;
    if (g_active[row]) {
        float* xr = g_x + (size_t)row * DDIM;
        for (int j = tid; j < DDIM; j += 256)
            if (__float_as_uint(fabsf(sh[j])) >= kb) xr[j] += sh[j];
    }
}

// ---------------- CEN (R1 structure) ----------------
__global__ void cen_score_kernel(const float* __restrict__ cohW,
                                 const float* __restrict__ cohb) {
    int row = blockIdx.x;
    if (!g_active[row]) return;
    int tid = threadIdx.x;
    __shared__ float red[256];
    float cb = cohb[0];
    for (int n = 0; n < NBR; n++) {
        const float* sr = g_sims + ((size_t)n * MTOK + row) * DDIM;
        float p = 0.f;
        for (int j = tid; j < DDIM; j += 256) p += sr[j] * cohW[j];
        red[tid] = p; __syncthreads();
        for (int s = 128; s > 0; s >>= 1) {
            if (tid < s) red[tid] += red[tid + s];
            __syncthreads();
        }
        if (tid == 0) atomicAdd(&g_scores[n], red[0] + cb);
        __syncthreads();
    }
}

__global__ void argmax_kernel() {
    if (threadIdx.x == 0) {
        int b = 0; float v = g_scores[0];
        if (g_scores[1] > v) { b = 1; v = g_scores[1]; }
        if (g_scores[2] > v) { b = 2; }
        g_best = b;
    }
}

__global__ void cen_add_kernel() {
    const float4* s4 = (const float4*)(g_sims + (size_t)g_best * MTOK * DDIM);
    float4* x4 = (float4*)g_x;
    int tid = blockIdx.x * blockDim.x + threadIdx.x, st = gridDim.x * blockDim.x;
    for (int i = tid; i < MTOK * DDIM / 4; i += st) {
        if (g_active[i >> 8]) {
            float4 a = x4[i], b = s4[i];
            a.x += b.x; a.y += b.y; a.z += b.z; a.w += b.w;
            x4[i] = a;
        }
    }
}

// ---------------- fused VLM loss (R1 exact, 378us measured) ----------------
__global__ __launch_bounds__(256) void vlm_kernel(
    const float* __restrict__ encW, const float* __restrict__ encb,
    const float* __restrict__ decW, const float* __restrict__ decb)
{
    __shared__ float xs[32][128];
    __shared__ float shid[32][64];
    __shared__ float red[256];
    int t0 = blockIdx.x * 32, tid = threadIdx.x;
    int sd = tid & 63, tg = tid >> 6;
    float acc[8];
#pragma unroll
    for (int u = 0; u < 8; u++) acc[u] = encb[sd];
    for (int kc = 0; kc < DDIM; kc += 128) {
        __syncthreads();
        for (int e = tid; e < 32 * 128; e += 256)
            xs[e >> 7][e & 127] = g_x[(size_t)(t0 + (e >> 7)) * DDIM + kc + (e & 127)];
        __syncthreads();
        for (int k = 0; k < 128; k++) {
            float w = encW[(size_t)(kc + k) * SDIM + sd];
#pragma unroll
            for (int u = 0; u < 8; u++) acc[u] = fmaf(xs[tg * 8 + u][k], w, acc[u]);
        }
    }
#pragma unroll
    for (int u = 0; u < 8; u++) shid[tg * 8 + u][sd] = fmaxf(acc[u], 0.f);
    __syncthreads();
    float sq = 0.f;
    for (int jj = 0; jj < 4; jj++) {
        int j = jj * 256 + tid;
        float wv[64];
#pragma unroll
        for (int s = 0; s < 64; s++) wv[s] = decW[(size_t)s * DDIM + j];
        float db = decb[j];
        for (int t = 0; t < 32; t++) {
            float r = db;
#pragma unroll
            for (int s = 0; s < 64; s++) r = fmaf(shid[t][s], wv[s], r);
            float d = r - g_x[(size_t)(t0 + t) * DDIM + j];
            sq = fmaf(d, d, sq);
        }
    }
    red[tid] = sq; __syncthreads();
    for (int s = 128; s > 0; s >>= 1) { if (tid < s) red[tid] += red[tid + s]; __syncthreads(); }
    if (tid == 0) atomicAdd(&g_vloss, (double)red[0]);
}

// ---------------- exit head confidence ----------------
__global__ void exit_kernel(const float* __restrict__ out) {
    int row = blockIdx.x;
    if (!g_active[row]) return;
    int tid = threadIdx.x;
    const float* lr = out + (size_t)row * CCLS;
    __shared__ float red[256];
    float mx = -1e30f;
    for (int j = tid; j < CCLS; j += 256) mx = fmaxf(mx, lr[j]);
    red[tid] = mx; __syncthreads();
    for (int s = 128; s > 0; s >>= 1) { if (tid < s) red[tid] = fmaxf(red[tid], red[tid + s]); __syncthreads(); }
    float m = red[0]; __syncthreads();
    float se = 0.f;
    for (int j = tid; j < CCLS; j += 256) se += expf(lr[j] - m);
    red[tid] = se; __syncthreads();
    for (int s = 128; s > 0; s >>= 1) { if (tid < s) red[tid] += red[tid + s]; __syncthreads(); }
    float conf = 1.0f / red[0];
    if (tid == 0) { g_depth[row]++; g_active[row] = (conf < THRC) ? 1 : 0; }
}

__global__ void finalize_kernel(float* __restrict__ out, int base) {
    __shared__ int red[256];
    int tid = threadIdx.x, s = 0;
    for (int i = tid; i < MTOK; i += 256) s += g_depth[i];
    red[tid] = s; __syncthreads();
    for (int w = 128; w > 0; w >>= 1) { if (tid < w) red[tid] += red[tid + w]; __syncthreads(); }
    if (tid == 0) {
        out[base + 0] = (float)red[0] / (float)MTOK;
        out[base + 1] = (float)(g_vloss / ((double)LNUM * (double)MTOK * (double)DDIM));
    }
}

extern "C" void kernel_launch(void* const* d_in, const int* in_sizes, int n_in,
                              void* d_out, int out_size) {
    const float* x = (const float*)d_in[0];
    const float* dcaW = (const float*)d_in[1];
    const float* dcab = (const float*)d_in[2];
    const float* exW = (const float*)d_in[3];
    const float* exb = (const float*)d_in[4];
    const float* cenW = (const float*)d_in[5];
    const float* cenb = (const float*)d_in[6];
    const float* cohW = (const float*)d_in[7];
    const float* cohb = (const float*)d_in[8];
    const float* encW = (const float*)d_in[9];
    const float* encb = (const float*)d_in[10];
    const float* decW = (const float*)d_in[11];
    const float* decb = (const float*)d_in[12];
    float* out = (float*)d_out;

    float *px, *ph, *ps;
    unsigned char* pact;
    cudaGetSymbolAddress((void**)&px, g_x);
    cudaGetSymbolAddress((void**)&ph, g_h);
    cudaGetSymbolAddress((void**)&ps, g_sims);
    cudaGetSymbolAddress((void**)&pact, g_active);

    // one-time stream/event creation (first call is the uncaptured correctness run)
    static cudaStream_t s_vlm = 0;
    static cudaEvent_t evF[LNUM], evJ[LNUM];
    static bool inited = false;
    if (!inited) {
        cudaStreamCreateWithFlags(&s_vlm, cudaStreamNonBlocking);
        for (int i = 0; i < LNUM; i++) {
            cudaEventCreateWithFlags(&evF[i], cudaEventDisableTiming);
            cudaEventCreateWithFlags(&evJ[i], cudaEventDisableTiming);
        }
        inited = true;
    }

    init_kernel<<<2048, 256>>>(x);

    dim3 gg(8, 128);
    cudaEvent_t prevJ = 0;

    for (int i = 0; i < LNUM; i++) {
        // SparseDCA (flip-sensitive): scalar fp32, bitwise-R1 trajectory
        sgemm_kernel<1><<<gg, 256>>>(
            px, dcaW + (size_t)i * DDIM * DDIM, dcab + (size_t)i * DDIM,
            ph, MTOK, DDIM, DDIM, (const unsigned char*)0);
        // join previous layer's vlm before topk mutates g_x
        if (prevJ) cudaStreamWaitEvent(0, prevJ, 0);
        topk_kernel<<<MTOK, 256>>>();

        if (i == LNUM / 2) {
            for (int n = 0; n < NBR; n++)
                sgemm_kernel<1><<<gg, 256>>>(
                    px, cenW + (size_t)n * DDIM * DDIM, cenb + (size_t)n * DDIM,
                    ps + (size_t)n * MTOK * DDIM, MTOK, DDIM, DDIM,
                    (const unsigned char*)0);
            cen_score_kernel<<<MTOK, 256>>>(cohW, cohb);
            argmax_kernel<<<1, 32>>>();
            cen_add_kernel<<<4096, 256>>>();
        }

        // fork vlm onto side stream; it overlaps exit GEMM + exit_kernel + next DCA
        cudaEventRecord(evF[i], 0);
        cudaStreamWaitEvent(s_vlm, evF[i], 0);
        vlm_kernel<<<MTOK / 32, 256, 0, s_vlm>>>(encW, encb, decW, decb);
        cudaEventRecord(evJ[i], s_vlm);
        prevJ = evJ[i];

        // exit head: scalar, active rows straight into d_out
        sgemm_kernel<2><<<gg, 256>>>(
            px, exW + (size_t)i * DDIM * CCLS, exb + (size_t)i * CCLS,
            out, MTOK, CCLS, DDIM, pact);
        exit_kernel<<<MTOK, 256>>>(out);
    }

    cudaStreamWaitEvent(0, prevJ, 0);
    finalize_kernel<<<1, 256>>>(out, out_size - 2);
}

// round 17
// speedup vs baseline: 1.1968x; 1.1968x over previous
#include <cuda_runtime.h>
#include <math.h>
#include <stdint.h>

#define MTOK 16384
#define DDIM 1024
#define CCLS 1000
#define LNUM 6
#define NBR  3
#define SDIM 64
#define KTOP 204
#define THRC 0.85f

__device__ float g_x[MTOK * DDIM];             // 64 MB
__device__ float g_h[MTOK * DDIM];             // 64 MB
__device__ float g_sims[NBR * MTOK * DDIM];    // 192 MB (guard-safe, proven)
__device__ unsigned char g_active[MTOK];
__device__ int g_depth[MTOK];
__device__ float g_scores[NBR];
__device__ int g_best;
__device__ double g_vloss;

__device__ __forceinline__ float gelu_exact(float v) {
    return 0.5f * v * (1.0f + erff(v * 0.70710678118654752440f));
}

__global__ void init_kernel(const float* __restrict__ x) {
    int tid = blockIdx.x * blockDim.x + threadIdx.x, st = gridDim.x * blockDim.x;
    const float4* x4 = (const float4*)x;
    float4* g4 = (float4*)g_x;
    for (int i = tid; i < MTOK * DDIM / 4; i += st) g4[i] = x4[i];
    for (int i = tid; i < MTOK; i += st) { g_active[i] = 1; g_depth[i] = 0; }
    if (tid == 0) { g_vloss = 0.0; g_best = 0; g_scores[0] = g_scores[1] = g_scores[2] = 0.f; }
}

// ---------------- R1 scalar fp32 SGEMM, BK=16 (bitwise-R1 trajectory) ----------------
// ACT 1: C = gelu(v + bias), all rows (DCA h, CEN sims)
// ACT 2: C = v + bias, rows with actmask!=0 only (exit head -> d_out)
template <int ACT>
__global__ __launch_bounds__(256) void sgemm_kernel(
    const float* __restrict__ A, const float* __restrict__ B,
    const float* __restrict__ bias, float* __restrict__ C,
    int M, int N, int K, const unsigned char* __restrict__ actmask)
{
    __shared__ float As[16][132];
    __shared__ float Bs[16][128];

    const int tid = threadIdx.x;
    const int bx = blockIdx.x, by = blockIdx.y;
    const float* Ab = A + (size_t)by * 128 * K;
    const int trow = tid >> 4, tcol = tid & 15;
    const int ar0 = tid >> 2, ac0 = (tid & 3) * 4;
    const int ar1 = ar0 + 64;
    const int bk0 = tid >> 5, bc0 = (tid & 31) * 4;
    const int bk1 = bk0 + 8;
    const int gcolB = bx * 128 + bc0;
    const bool bok = (gcolB < N);
    const float* Bp = B + gcolB;

    float acc[8][8];
#pragma unroll
    for (int i = 0; i < 8; i++)
#pragma unroll
        for (int j = 0; j < 8; j++) acc[i][j] = 0.f;

    float4 a0, a1, b0, b1;
    const float4 z4 = make_float4(0.f, 0.f, 0.f, 0.f);
    a0 = *(const float4*)(Ab + (size_t)ar0 * K + ac0);
    a1 = *(const float4*)(Ab + (size_t)ar1 * K + ac0);
    b0 = bok ? *(const float4*)(Bp + (size_t)bk0 * N) : z4;
    b1 = bok ? *(const float4*)(Bp + (size_t)bk1 * N) : z4;

    for (int k0 = 0; k0 < K; k0 += 16) {
        As[ac0 + 0][ar0] = a0.x; As[ac0 + 1][ar0] = a0.y;
        As[ac0 + 2][ar0] = a0.z; As[ac0 + 3][ar0] = a0.w;
        As[ac0 + 0][ar1] = a1.x; As[ac0 + 1][ar1] = a1.y;
        As[ac0 + 2][ar1] = a1.z; As[ac0 + 3][ar1] = a1.w;
        *(float4*)&Bs[bk0][bc0] = b0;
        *(float4*)&Bs[bk1][bc0] = b1;
        __syncthreads();

        if (k0 + 16 < K) {
            a0 = *(const float4*)(Ab + (size_t)ar0 * K + (k0 + 16) + ac0);
            a1 = *(const float4*)(Ab + (size_t)ar1 * K + (k0 + 16) + ac0);
            b0 = bok ? *(const float4*)(Bp + (size_t)(k0 + 16 + bk0) * N) : z4;
            b1 = bok ? *(const float4*)(Bp + (size_t)(k0 + 16 + bk1) * N) : z4;
        }

#pragma unroll
        for (int kk = 0; kk < 16; kk++) {
            float4 ra0 = *(const float4*)&As[kk][trow * 4];
            float4 ra1 = *(const float4*)&As[kk][64 + trow * 4];
            float4 rb0 = *(const float4*)&Bs[kk][tcol * 4];
            float4 rb1 = *(const float4*)&Bs[kk][64 + tcol * 4];
            float ra[8] = {ra0.x, ra0.y, ra0.z, ra0.w, ra1.x, ra1.y, ra1.z, ra1.w};
            float rb[8] = {rb0.x, rb0.y, rb0.z, rb0.w, rb1.x, rb1.y, rb1.z, rb1.w};
#pragma unroll
            for (int i = 0; i < 8; i++)
#pragma unroll
                for (int j = 0; j < 8; j++) acc[i][j] = fmaf(ra[i], rb[j], acc[i][j]);
        }
        __syncthreads();
    }

#pragma unroll
    for (int i = 0; i < 8; i++) {
        int row = by * 128 + ((i < 4) ? (trow * 4 + i) : (64 + trow * 4 + (i - 4)));
        bool wr = (ACT == 1) || (actmask[row] != 0);
        if (!wr) continue;
#pragma unroll
        for (int jq = 0; jq < 2; jq++) {
            int col = bx * 128 + (jq ? (64 + tcol * 4) : (tcol * 4));
            if (col + 3 < N) {
                float v0 = acc[i][jq * 4 + 0] + bias[col + 0];
                float v1 = acc[i][jq * 4 + 1] + bias[col + 1];
                float v2 = acc[i][jq * 4 + 2] + bias[col + 2];
                float v3 = acc[i][jq * 4 + 3] + bias[col + 3];
                if (ACT == 1) {
                    v0 = gelu_exact(v0); v1 = gelu_exact(v1);
                    v2 = gelu_exact(v2); v3 = gelu_exact(v3);
                }
                *(float4*)(C + (size_t)row * N + col) = make_float4(v0, v1, v2, v3);
            } else {
#pragma unroll
                for (int e = 0; e < 4; e++) {
                    int cc = col + e;
                    if (cc < N) {
                        float v = acc[i][jq * 4 + e] + bias[cc];
                        if (ACT == 1) v = gelu_exact(v);
                        C[(size_t)row * N + cc] = v;
                    }
                }
            }
        }
    }
}

// ---------------- per-token exact top-K + masked residual add ----------------
__global__ void topk_kernel() {
    int row = blockIdx.x, tid = threadIdx.x;
    __shared__ float sh[DDIM];
    __shared__ int hist[256];
    __shared__ int s_k;
    __shared__ unsigned s_pref;
    const float* hr = g_h + (size_t)row * DDIM;
    for (int j = tid; j < DDIM; j += 256) sh[j] = hr[j];
    if (tid == 0) { s_k = KTOP; s_pref = 0u; }
    __syncthreads();
    for (int shift = 24; shift >= 0; shift -= 8) {
        hist[tid] = 0;
        __syncthreads();
        unsigned pref = s_pref;
        for (int j = tid; j < DDIM; j += 256) {
            unsigned b = __float_as_uint(fabsf(sh[j]));
            bool cand = (shift == 24) || ((b >> (shift + 8)) == pref);
            if (cand) atomicAdd(&hist[(b >> shift) & 255], 1);
        }
        __syncthreads();
        if (tid == 0) {
            int k = s_k, cum = 0, d = 255;
            for (; d >= 0; --d) { cum += hist[d]; if (cum >= k) break; }
            s_k = k - (cum - hist[d]);
            s_pref = (pref << 8) | (unsigned)d;
        }
        __syncthreads();
    }
    unsigned kb = s_pref;
    if (g_active[row]) {
        float* xr = g_x + (size_t)row * DDIM;
        for (int j = tid; j < DDIM; j += 256)
            if (__float_as_uint(fabsf(sh[j])) >= kb) xr[j] += sh[j];
    }
}

// ---------------- CEN (R1 structure) ----------------
__global__ void cen_score_kernel(const float* __restrict__ cohW,
                                 const float* __restrict__ cohb) {
    int row = blockIdx.x;
    if (!g_active[row]) return;
    int tid = threadIdx.x;
    __shared__ float red[256];
    float cb = cohb[0];
    for (int n = 0; n < NBR; n++) {
        const float* sr = g_sims + ((size_t)n * MTOK + row) * DDIM;
        float p = 0.f;
        for (int j = tid; j < DDIM; j += 256) p += sr[j] * cohW[j];
        red[tid] = p; __syncthreads();
        for (int s = 128; s > 0; s >>= 1) {
            if (tid < s) red[tid] += red[tid + s];
            __syncthreads();
        }
        if (tid == 0) atomicAdd(&g_scores[n], red[0] + cb);
        __syncthreads();
    }
}

__global__ void argmax_kernel() {
    if (threadIdx.x == 0) {
        int b = 0; float v = g_scores[0];
        if (g_scores[1] > v) { b = 1; v = g_scores[1]; }
        if (g_scores[2] > v) { b = 2; }
        g_best = b;
    }
}

__global__ void cen_add_kernel() {
    const float4* s4 = (const float4*)(g_sims + (size_t)g_best * MTOK * DDIM);
    float4* x4 = (float4*)g_x;
    int tid = blockIdx.x * blockDim.x + threadIdx.x, st = gridDim.x * blockDim.x;
    for (int i = tid; i < MTOK * DDIM / 4; i += st) {
        if (g_active[i >> 8]) {
            float4 a = x4[i], b = s4[i];
            a.x += b.x; a.y += b.y; a.z += b.z; a.w += b.w;
            x4[i] = a;
        }
    }
}

// ---------------- fused VLM loss (R1 exact) ----------------
__global__ __launch_bounds__(256) void vlm_kernel(
    const float* __restrict__ encW, const float* __restrict__ encb,
    const float* __restrict__ decW, const float* __restrict__ decb)
{
    __shared__ float xs[32][128];
    __shared__ float shid[32][64];
    __shared__ float red[256];
    int t0 = blockIdx.x * 32, tid = threadIdx.x;
    int sd = tid & 63, tg = tid >> 6;
    float acc[8];
#pragma unroll
    for (int u = 0; u < 8; u++) acc[u] = encb[sd];
    for (int kc = 0; kc < DDIM; kc += 128) {
        __syncthreads();
        for (int e = tid; e < 32 * 128; e += 256)
            xs[e >> 7][e & 127] = g_x[(size_t)(t0 + (e >> 7)) * DDIM + kc + (e & 127)];
        __syncthreads();
        for (int k = 0; k < 128; k++) {
            float w = encW[(size_t)(kc + k) * SDIM + sd];
#pragma unroll
            for (int u = 0; u < 8; u++) acc[u] = fmaf(xs[tg * 8 + u][k], w, acc[u]);
        }
    }
#pragma unroll
    for (int u = 0; u < 8; u++) shid[tg * 8 + u][sd] = fmaxf(acc[u], 0.f);
    __syncthreads();
    float sq = 0.f;
    for (int jj = 0; jj < 4; jj++) {
        int j = jj * 256 + tid;
        float wv[64];
#pragma unroll
        for (int s = 0; s < 64; s++) wv[s] = decW[(size_t)s * DDIM + j];
        float db = decb[j];
        for (int t = 0; t < 32; t++) {
            float r = db;
#pragma unroll
            for (int s = 0; s < 64; s++) r = fmaf(shid[t][s], wv[s], r);
            float d = r - g_x[(size_t)(t0 + t) * DDIM + j];
            sq = fmaf(d, d, sq);
        }
    }
    red[tid] = sq; __syncthreads();
    for (int s = 128; s > 0; s >>= 1) { if (tid < s) red[tid] += red[tid + s]; __syncthreads(); }
    if (tid == 0) atomicAdd(&g_vloss, (double)red[0]);
}

// ---------------- exit head confidence (reads active rows of d_out) ----------------
__global__ void exit_kernel(const float* __restrict__ out) {
    int row = blockIdx.x;
    if (!g_active[row]) return;
    int tid = threadIdx.x;
    const float* lr = out + (size_t)row * CCLS;
    __shared__ float red[256];
    float mx = -1e30f;
    for (int j = tid; j < CCLS; j += 256) mx = fmaxf(mx, lr[j]);
    red[tid] = mx; __syncthreads();
    for (int s = 128; s > 0; s >>= 1) { if (tid < s) red[tid] = fmaxf(red[tid], red[tid + s]); __syncthreads(); }
    float m = red[0]; __syncthreads();
    float se = 0.f;
    for (int j = tid; j < CCLS; j += 256) se += expf(lr[j] - m);
    red[tid] = se; __syncthreads();
    for (int s = 128; s > 0; s >>= 1) { if (tid < s) red[tid] += red[tid + s]; __syncthreads(); }
    float conf = 1.0f / red[0];
    if (tid == 0) { g_depth[row]++; g_active[row] = (conf < THRC) ? 1 : 0; }
}

__global__ void finalize_kernel(float* __restrict__ out, int base) {
    __shared__ int red[256];
    int tid = threadIdx.x, s = 0;
    for (int i = tid; i < MTOK; i += 256) s += g_depth[i];
    red[tid] = s; __syncthreads();
    for (int w = 128; w > 0; w >>= 1) { if (tid < w) red[tid] += red[tid + w]; __syncthreads(); }
    if (tid == 0) {
        out[base + 0] = (float)red[0] / (float)MTOK;
        out[base + 1] = (float)(g_vloss / ((double)LNUM * (double)MTOK * (double)DDIM));
    }
}

extern "C" void kernel_launch(void* const* d_in, const int* in_sizes, int n_in,
                              void* d_out, int out_size) {
    const float* x = (const float*)d_in[0];
    const float* dcaW = (const float*)d_in[1];
    const float* dcab = (const float*)d_in[2];
    const float* exW = (const float*)d_in[3];
    const float* exb = (const float*)d_in[4];
    const float* cenW = (const float*)d_in[5];
    const float* cenb = (const float*)d_in[6];
    const float* cohW = (const float*)d_in[7];
    const float* cohb = (const float*)d_in[8];
    const float* encW = (const float*)d_in[9];
    const float* encb = (const float*)d_in[10];
    const float* decW = (const float*)d_in[11];
    const float* decb = (const float*)d_in[12];
    float* out = (float*)d_out;

    float *px, *ph, *ps;
    unsigned char* pact;
    cudaGetSymbolAddress((void**)&px, g_x);
    cudaGetSymbolAddress((void**)&ph, g_h);
    cudaGetSymbolAddress((void**)&ps, g_sims);
    cudaGetSymbolAddress((void**)&pact, g_active);

    // one-time stream/event creation (first call is the uncaptured correctness run)
    static cudaStream_t s_vlm = 0;
    static cudaEvent_t evF[LNUM], evJ[LNUM];
    static bool inited = false;
    if (!inited) {
        cudaStreamCreateWithFlags(&s_vlm, cudaStreamNonBlocking);
        for (int i = 0; i < LNUM; i++) {
            cudaEventCreateWithFlags(&evF[i], cudaEventDisableTiming);
            cudaEventCreateWithFlags(&evJ[i], cudaEventDisableTiming);
        }
        inited = true;
    }

    init_kernel<<<2048, 256>>>(x);

    dim3 gg(8, 128);
    cudaEvent_t prevJ = 0;

    for (int i = 0; i < LNUM; i++) {
        // SparseDCA (flip-sensitive): scalar fp32, bitwise-R1 trajectory
        sgemm_kernel<1><<<gg, 256>>>(
            px, dcaW + (size_t)i * DDIM * DDIM, dcab + (size_t)i * DDIM,
            ph, MTOK, DDIM, DDIM, (const unsigned char*)0);
        // join previous layer's vlm before topk mutates g_x
        if (prevJ) cudaStreamWaitEvent(0, prevJ, 0);
        topk_kernel<<<MTOK, 256>>>();

        if (i == LNUM / 2) {
            for (int n = 0; n < NBR; n++)
                sgemm_kernel<1><<<gg, 256>>>(
                    px, cenW + (size_t)n * DDIM * DDIM, cenb + (size_t)n * DDIM,
                    ps + (size_t)n * MTOK * DDIM, MTOK, DDIM, DDIM,
                    (const unsigned char*)0);
            cen_score_kernel<<<MTOK, 256>>>(cohW, cohb);
            argmax_kernel<<<1, 32>>>();
            cen_add_kernel<<<4096, 256>>>();
        }

        // fork vlm onto side stream; overlaps exit GEMM + exit_kernel + next DCA
        cudaEventRecord(evF[i], 0);
        cudaStreamWaitEvent(s_vlm, evF[i], 0);
        vlm_kernel<<<MTOK / 32, 256, 0, s_vlm>>>(encW, encb, decW, decb);
        cudaEventRecord(evJ[i], s_vlm);
        prevJ = evJ[i];

        // exit head: scalar, active rows straight into d_out
        sgemm_kernel<2><<<gg, 256>>>(
            px, exW + (size_t)i * DDIM * CCLS, exb + (size_t)i * CCLS,
            out, MTOK, CCLS, DDIM, pact);
        exit_kernel<<<MTOK, 256>>>(out);
    }

    cudaStreamWaitEvent(0, prevJ, 0);
    finalize_kernel<<<1, 256>>>(out, out_size - 2);
}